// round 9
// baseline (speedup 1.0000x reference)
#include <cuda_runtime.h>
#include <cuda_bf16.h>
#include <cstdint>
#include <stdint.h>
#include <math.h>

#define Bb 16
#define Nn 1024
#define Dd 512
#define Kk 8
#define NITER 3
#define NCH 16           // n-chunks per batch (64 rows each)

#define Mtot (Bb*Nn)     // 16384
#define Ntot (2*Dd)      // 1024
#define LDA 40           // smem row stride (bf16): 32 + 8 pad, conflict-free ldmatrix
#define TILE_B (128*LDA*2)   // one 128x32 bf16 tile w/ pad = 10240 bytes
#define MMA_SMEM (2*4*TILE_B) // 2 stages x 4 tiles = 81920

__device__ __constant__ float c_EPS = 1e-8f;
__device__ __constant__ float c_LNEPS = 1e-5f;
__device__ __constant__ float c_LOG2PI = 1.8378770664093453f;

// ---------------- scratch ----------------------------------------------------
__device__ float g_keys[Mtot*Dd];
__device__ float g_values[Mtot*Dd];
__device__ float g_q[Bb*Kk*Dd];
__device__ float g_sigma[Bb*Kk*Dd];
__device__ float g_w[Bb*Kk*Dd];
__device__ float g_qw[Bb*Kk*Dd];
__device__ float g_c1[Bb*Kk];
__device__ float g_mixing[Bb*Kk];
__device__ float g_attn[Bb*Nn*Kk];
__device__ float g_Spart[Bb*NCH*Kk];
__device__ float g_S[Bb*Kk];
__device__ float g_mupart[NCH*Bb*Kk*Dd];
__device__ float g_v2part[NCH*Bb*Kk*Dd];
__device__ float g_mu[Bb*Kk*Dd];

__device__ __align__(16) __nv_bfloat16 g_Ahi[Mtot*Dd];
__device__ __align__(16) __nv_bfloat16 g_Alo[Mtot*Dd];
__device__ __align__(16) __nv_bfloat16 g_Bhi[Ntot*Dd];
__device__ __align__(16) __nv_bfloat16 g_Blo[Ntot*Dd];

// ---------------- PTX helpers ------------------------------------------------
__device__ __forceinline__ uint32_t smem_u32(const void* p) {
    uint32_t a;
    asm("{ .reg .u64 t; cvta.to.shared.u64 t, %1; cvt.u32.u64 %0, t; }" : "=r"(a) : "l"(p));
    return a;
}
__device__ __forceinline__ void cpasync16(uint32_t saddr, const void* g) {
    asm volatile("cp.async.ca.shared.global [%0], [%1], 16;" :: "r"(saddr), "l"(g));
}
__device__ __forceinline__ void ldm4(uint32_t* r, uint32_t addr) {
    asm volatile("ldmatrix.sync.aligned.m8n8.x4.shared.b16 {%0,%1,%2,%3}, [%4];"
        : "=r"(r[0]), "=r"(r[1]), "=r"(r[2]), "=r"(r[3]) : "r"(addr));
}
__device__ __forceinline__ void mma16816(float* c, const uint32_t* a, const uint32_t* b) {
    asm volatile(
        "mma.sync.aligned.m16n8k16.row.col.f32.bf16.bf16.f32 "
        "{%0,%1,%2,%3}, {%4,%5,%6,%7}, {%8,%9}, {%0,%1,%2,%3};"
        : "+f"(c[0]), "+f"(c[1]), "+f"(c[2]), "+f"(c[3])
        : "r"(a[0]), "r"(a[1]), "r"(a[2]), "r"(a[3]), "r"(b[0]), "r"(b[1]));
}

// ---------------- K0: LN stats + bf16 hi/lo split ----------------------------
__global__ __launch_bounds__(128) void ln_split(
    const float* __restrict__ E, const float* __restrict__ lng, const float* __restrict__ lnb)
{
    int row = blockIdx.x;
    int t = threadIdx.x;
    float4 v = ((const float4*)(E + (size_t)row * Dd))[t];
    float s = v.x + v.y + v.z + v.w;
    float s2 = v.x*v.x + v.y*v.y + v.z*v.z + v.w*v.w;
    #pragma unroll
    for (int o = 16; o; o >>= 1) {
        s  += __shfl_xor_sync(0xffffffffu, s,  o);
        s2 += __shfl_xor_sync(0xffffffffu, s2, o);
    }
    __shared__ float sh[2][4];
    if ((t & 31) == 0) { sh[0][t >> 5] = s; sh[1][t >> 5] = s2; }
    __syncthreads();
    float S  = sh[0][0] + sh[0][1] + sh[0][2] + sh[0][3];
    float S2 = sh[1][0] + sh[1][1] + sh[1][2] + sh[1][3];
    float m = S / (float)Dd;
    float var = S2 / (float)Dd - m * m;
    float rs = rsqrtf(var + c_LNEPS);

    float4 g4 = ((const float4*)lng)[t];
    float4 b4 = ((const float4*)lnb)[t];
    float y[4];
    y[0] = (v.x - m) * rs * g4.x + b4.x;
    y[1] = (v.y - m) * rs * g4.y + b4.y;
    y[2] = (v.z - m) * rs * g4.z + b4.z;
    y[3] = (v.w - m) * rs * g4.w + b4.w;
    __nv_bfloat16 hi[4], lo[4];
    #pragma unroll
    for (int i = 0; i < 4; i++) {
        hi[i] = __float2bfloat16(y[i]);
        lo[i] = __float2bfloat16(y[i] - __bfloat162float(hi[i]));
    }
    *(uint2*)(g_Ahi + (size_t)row * Dd + t * 4) = *(uint2*)hi;
    *(uint2*)(g_Alo + (size_t)row * Dd + t * 4) = *(uint2*)lo;
}

// ---------------- K1: W^T bf16 hi/lo split -----------------------------------
__global__ void wt_split(const float* __restrict__ Wk, const float* __restrict__ Wv) {
    __shared__ float tile[32][33];
    int n0 = blockIdx.x * 32;
    int k0 = blockIdx.y * 32;
    const float* W = (n0 < Dd) ? Wk : Wv;
    int nc0 = n0 & (Dd - 1);
    int tx = threadIdx.x, ty = threadIdx.y;
    #pragma unroll
    for (int i = ty; i < 32; i += 8)
        tile[i][tx] = W[(size_t)(k0 + i) * Dd + nc0 + tx];
    __syncthreads();
    #pragma unroll
    for (int i = ty; i < 32; i += 8) {
        float x = tile[tx][i];
        __nv_bfloat16 hi = __float2bfloat16(x);
        __nv_bfloat16 lo = __float2bfloat16(x - __bfloat162float(hi));
        g_Bhi[(size_t)(n0 + i) * Dd + k0 + tx] = hi;
        g_Blo[(size_t)(n0 + i) * Dd + k0 + tx] = lo;
    }
}

// ---------------- K2: HMMA bf16x3 GEMM, tiles resident for all 3 passes ------
__global__ __launch_bounds__(256, 2) void mma_kv(
    const float* __restrict__ bk, const float* __restrict__ bv)
{
    extern __shared__ char dsm[];
    int tid = threadIdx.x, lane = tid & 31, wid = tid >> 5;
    int warp_m = wid >> 1, warp_n = wid & 1;
    int n0 = blockIdx.x * 128;
    int m0 = blockIdx.y * 128;

    float acc[2][8][4];
    #pragma unroll
    for (int i = 0; i < 2; i++)
        #pragma unroll
        for (int j = 0; j < 8; j++)
            #pragma unroll
            for (int q = 0; q < 4; q++) acc[i][j][q] = 0.f;

    const int lrow = tid >> 1;            // 0..127
    const int lseg = (tid & 1) * 2;       // segs lseg, lseg+1 (16B each)

    // prefetch chunk 0
    #pragma unroll
    for (int j = 0; j < 2; j++) {
        int off = (lseg + j) * 8;
        size_t ao = (size_t)(m0 + lrow) * Dd + off;
        size_t bo = (size_t)(n0 + lrow) * Dd + off;
        uint32_t so = lrow * LDA * 2 + off * 2;   // byte offset within tile
        cpasync16(smem_u32(dsm + 0*TILE_B + so), g_Ahi + ao);
        cpasync16(smem_u32(dsm + 1*TILE_B + so), g_Alo + ao);
        cpasync16(smem_u32(dsm + 2*TILE_B + so), g_Bhi + bo);
        cpasync16(smem_u32(dsm + 3*TILE_B + so), g_Blo + bo);
    }
    asm volatile("cp.async.commit_group;" ::: "memory");

    for (int kc = 0; kc < 16; kc++) {
        int buf = kc & 1;
        char* cur = dsm + buf * 4 * TILE_B;
        if (kc < 15) {
            char* nxt = dsm + (buf ^ 1) * 4 * TILE_B;
            int kn = (kc + 1) * 32;
            #pragma unroll
            for (int j = 0; j < 2; j++) {
                int off = (lseg + j) * 8;
                size_t ao = (size_t)(m0 + lrow) * Dd + kn + off;
                size_t bo = (size_t)(n0 + lrow) * Dd + kn + off;
                uint32_t so = lrow * LDA * 2 + off * 2;
                cpasync16(smem_u32(nxt + 0*TILE_B + so), g_Ahi + ao);
                cpasync16(smem_u32(nxt + 1*TILE_B + so), g_Alo + ao);
                cpasync16(smem_u32(nxt + 2*TILE_B + so), g_Bhi + bo);
                cpasync16(smem_u32(nxt + 3*TILE_B + so), g_Blo + bo);
            }
            asm volatile("cp.async.commit_group;" ::: "memory");
            asm volatile("cp.async.wait_group 1;" ::: "memory");
        } else {
            asm volatile("cp.async.wait_group 0;" ::: "memory");
        }
        __syncthreads();

        const __nv_bfloat16* sAhi = (const __nv_bfloat16*)(cur + 0*TILE_B);
        const __nv_bfloat16* sAlo = (const __nv_bfloat16*)(cur + 1*TILE_B);
        const __nv_bfloat16* sBhi = (const __nv_bfloat16*)(cur + 2*TILE_B);
        const __nv_bfloat16* sBlo = (const __nv_bfloat16*)(cur + 3*TILE_B);

        #pragma unroll
        for (int ks = 0; ks < 2; ks++) {
            uint32_t ahi[2][4], alo[2][4];
            #pragma unroll
            for (int mi = 0; mi < 2; mi++) {
                int row = warp_m * 32 + mi * 16 + (lane & 15);
                int col = ks * 16 + (lane >> 4) * 8;
                ldm4(ahi[mi], smem_u32(&sAhi[row * LDA + col]));
                ldm4(alo[mi], smem_u32(&sAlo[row * LDA + col]));
            }
            #pragma unroll
            for (int h = 0; h < 2; h++) {
                uint32_t bhi[4][2], blo[4][2];
                #pragma unroll
                for (int jj = 0; jj < 2; jj++) {
                    int nrow = warp_n * 64 + h * 32 + jj * 16 + (lane & 7) + ((lane >> 4) << 3);
                    int col = ks * 16 + ((lane >> 3) & 1) * 8;
                    uint32_t r4[4];
                    ldm4(r4, smem_u32(&sBhi[nrow * LDA + col]));
                    bhi[2*jj][0] = r4[0]; bhi[2*jj][1] = r4[1];
                    bhi[2*jj+1][0] = r4[2]; bhi[2*jj+1][1] = r4[3];
                    ldm4(r4, smem_u32(&sBlo[nrow * LDA + col]));
                    blo[2*jj][0] = r4[0]; blo[2*jj][1] = r4[1];
                    blo[2*jj+1][0] = r4[2]; blo[2*jj+1][1] = r4[3];
                }
                #pragma unroll
                for (int mi = 0; mi < 2; mi++)
                    #pragma unroll
                    for (int j2 = 0; j2 < 4; j2++) {
                        int nj = h * 4 + j2;
                        mma16816(acc[mi][nj], ahi[mi], bhi[j2]);
                        mma16816(acc[mi][nj], ahi[mi], blo[j2]);
                        mma16816(acc[mi][nj], alo[mi], bhi[j2]);
                    }
            }
        }
        __syncthreads();
    }

    // epilogue
    const bool isK = (n0 < Dd);
    float* Dst = isK ? g_keys : g_values;
    const float* bias = isK ? bk : bv;
    int nbase = (isK ? n0 : n0 - Dd) + warp_n * 64;
    int mbase = m0 + warp_m * 32;
    int r = lane >> 2, cp = 2 * (lane & 3);
    #pragma unroll
    for (int mi = 0; mi < 2; mi++) {
        #pragma unroll
        for (int nj = 0; nj < 8; nj++) {
            int n = nbase + nj * 8 + cp;
            float b0 = bias[n], b1 = bias[n + 1];
            int m = mbase + mi * 16 + r;
            float2 o0 = { acc[mi][nj][0] + b0, acc[mi][nj][1] + b1 };
            float2 o1 = { acc[mi][nj][2] + b0, acc[mi][nj][3] + b1 };
            *(float2*)&Dst[(size_t)m * Dd + n] = o0;
            *(float2*)&Dst[(size_t)(m + 8) * Dd + n] = o1;
        }
    }
}

// ---------------- K3: slots, queries, AND iter-0 prep (w/qw/c1) --------------
__global__ void init_slots_queries(
    const float* __restrict__ noise_init, const float* __restrict__ slots_mu,
    const float* __restrict__ slots_ls,   const float* __restrict__ mix_in,
    const float* __restrict__ Wq,         const float* __restrict__ bq)
{
    int bk_ = blockIdx.x;                 // 0..127
    int b = bk_ >> 3, k = bk_ & 7;
    __shared__ float slot[Dd];
    int t = threadIdx.x;                  // 128
    for (int d = t; d < Dd; d += 128) {
        float sg = expf(slots_ls[k * Dd + d]);
        slot[d] = slots_mu[k * Dd + d] + sg * noise_init[((size_t)b * Kk + k) * Dd + d];
        g_sigma[((size_t)b * Kk + k) * Dd + d] = sg;
    }
    if (t == 0) g_mixing[b * Kk + k] = mix_in[k];
    __syncthreads();
    float slog = 0.f, sqwq = 0.f;
    for (int j = t; j < Dd; j += 128) {
        float acc = bq[j];
        for (int d = 0; d < Dd; d++) acc += slot[d] * Wq[(size_t)d * Dd + j];
        g_q[((size_t)bk_) * Dd + j] = acc;
        float sg = g_sigma[(size_t)bk_ * Dd + j];
        float w = 1.f / (sg * sg + c_EPS);
        g_w [(size_t)bk_ * Dd + j] = w;
        g_qw[(size_t)bk_ * Dd + j] = acc * w;
        slog += logf(fabsf(sg) + c_EPS);
        sqwq += acc * acc * w;
    }
    #pragma unroll
    for (int o = 16; o; o >>= 1) {
        slog += __shfl_xor_sync(0xffffffffu, slog, o);
        sqwq += __shfl_xor_sync(0xffffffffu, sqwq, o);
    }
    __shared__ float sh[2][4];
    if ((t & 31) == 0) { sh[0][t >> 5] = slog; sh[1][t >> 5] = sqwq; }
    __syncthreads();
    if (t == 0) {
        float SL = sh[0][0] + sh[0][1] + sh[0][2] + sh[0][3];
        float SQ = sh[1][0] + sh[1][1] + sh[1][2] + sh[1][3];
        g_c1[bk_] = -0.5f * (float)Dd * c_LOG2PI - 0.5f * SL - 0.5f * SQ;
    }
}

// ---------------- K4: fused EM iteration (gll + attn + mu/v2 partials) -------
// grid (Bb, NCH), 256 thr; each block handles 64 rows.
__global__ __launch_bounds__(256) void em_iter() {
    int b = blockIdx.x, ch = blockIdx.y;
    int t = threadIdx.x, warp = t >> 5, lane = t & 31;
    __shared__ float sw[Kk * Dd];
    __shared__ float sqw[Kk * Dd];
    __shared__ float satt[64][Kk];
    __shared__ float wcs[8][Kk];
    __shared__ float c1s[Kk], mixs[Kk];
    for (int i = t; i < Kk * Dd; i += 256) {
        sw [i] = g_w [(size_t)b * Kk * Dd + i];
        sqw[i] = g_qw[(size_t)b * Kk * Dd + i];
    }
    if (t < Kk) { c1s[t] = g_c1[b * Kk + t]; mixs[t] = g_mixing[b * Kk + t]; }
    __syncthreads();

    // Phase A: attn for this block's 64 rows; warp handles rows [warp*8, warp*8+8)
    float cs8[Kk];
    #pragma unroll
    for (int k = 0; k < Kk; k++) cs8[k] = 0.f;

    int rbase = ch * 64 + warp * 8;
    for (int g = 0; g < 2; g++) {
        int r0 = rbase + g * 4;
        const float* kb = g_keys + ((size_t)b * Nn + r0) * Dd;
        float akk[4][Kk], akq[4][Kk];
        #pragma unroll
        for (int r = 0; r < 4; r++)
            #pragma unroll
            for (int k = 0; k < Kk; k++) { akk[r][k] = 0.f; akq[r][k] = 0.f; }
        #pragma unroll
        for (int i = 0; i < 16; i++) {
            int d = lane + 32 * i;
            float kv0 = kb[d], kv1 = kb[Dd + d], kv2 = kb[2*Dd + d], kv3 = kb[3*Dd + d];
            float q0 = kv0*kv0, q1 = kv1*kv1, q2 = kv2*kv2, q3 = kv3*kv3;
            #pragma unroll
            for (int k = 0; k < Kk; k++) {
                float w = sw[k * Dd + d], qw = sqw[k * Dd + d];
                akk[0][k] += q0 * w;  akq[0][k] += kv0 * qw;
                akk[1][k] += q1 * w;  akq[1][k] += kv1 * qw;
                akk[2][k] += q2 * w;  akq[2][k] += kv2 * qw;
                akk[3][k] += q3 * w;  akq[3][k] += kv3 * qw;
            }
        }
        float p[4][Kk];
        #pragma unroll
        for (int r = 0; r < 4; r++)
            #pragma unroll
            for (int k = 0; k < Kk; k++) p[r][k] = akq[r][k] - 0.5f * akk[r][k];
        #pragma unroll
        for (int o = 16; o; o >>= 1)
            #pragma unroll
            for (int r = 0; r < 4; r++)
                #pragma unroll
                for (int k = 0; k < Kk; k++)
                    p[r][k] += __shfl_xor_sync(0xffffffffu, p[r][k], o);
        // all lanes now hold full sums; compute attn per row
        #pragma unroll
        for (int r = 0; r < 4; r++) {
            float au[Kk], rsum = 0.f;
            #pragma unroll
            for (int k = 0; k < Kk; k++) {
                au[k] = mixs[k] * (c1s[k] + p[r][k]);
                rsum += au[k];
            }
            float inv = 1.f / rsum;
            float a[Kk];
            #pragma unroll
            for (int k = 0; k < Kk; k++) {
                a[k] = au[k] * inv;
                cs8[k] += a[k];
            }
            if (lane == 0) {
                int lr = warp * 8 + g * 4 + r;
                #pragma unroll
                for (int k = 0; k < Kk; k++) satt[lr][k] = a[k];
                float* arow = g_attn + ((size_t)b * Nn + ch * 64 + lr) * Kk;
                float4 a0 = { a[0], a[1], a[2], a[3] };
                float4 a1 = { a[4], a[5], a[6], a[7] };
                *(float4*)arow = a0;
                *(float4*)(arow + 4) = a1;
            }
        }
    }
    if (lane == 0) {
        #pragma unroll
        for (int k = 0; k < Kk; k++) wcs[warp][k] = cs8[k];
    }
    __syncthreads();
    if (t < Kk) {
        float S = 0.f;
        #pragma unroll
        for (int w = 0; w < 8; w++) S += wcs[w][t];   // fixed order
        g_Spart[((size_t)b * NCH + ch) * Kk + t] = S;
    }

    // Phase B: mu / E[v^2] partials; thread owns 2 d values
    int d0 = t * 2;
    float mu_[Kk][2], v2_[Kk][2];
    #pragma unroll
    for (int k = 0; k < Kk; k++) { mu_[k][0]=0.f; mu_[k][1]=0.f; v2_[k][0]=0.f; v2_[k][1]=0.f; }
    const float* vb = g_values + ((size_t)b * Nn + ch * 64) * Dd;
    for (int r = 0; r < 64; r++) {
        float2 v = *(const float2*)(vb + (size_t)r * Dd + d0);
        float vx2 = v.x * v.x, vy2 = v.y * v.y;
        #pragma unroll
        for (int k = 0; k < Kk; k++) {
            float a = satt[r][k];
            mu_[k][0] += a * v.x;  mu_[k][1] += a * v.y;
            v2_[k][0] += a * vx2;  v2_[k][1] += a * vy2;
        }
    }
    #pragma unroll
    for (int k = 0; k < Kk; k++) {
        size_t idx = (((size_t)ch * Bb + b) * Kk + k) * Dd + d0;
        *(float2*)(g_mupart + idx) = *(float2*)mu_[k];
        *(float2*)(g_v2part + idx) = *(float2*)v2_[k];
    }
}

// ---------------- K5: reduce partials; update mu/sigma/mixing + next prep ----
__global__ void reduce_update() {
    int bk_ = blockIdx.x;                  // 0..127
    int b = bk_ >> 3, k = bk_ & 7;
    int t = threadIdx.x;                   // 128
    float S = 0.f;
    #pragma unroll
    for (int c = 0; c < NCH; c++)
        S += g_Spart[((size_t)b * NCH + c) * Kk + k];   // fixed order
    float denom = S + c_EPS;
    float s = S / denom;
    float slog = 0.f, sqwq = 0.f;
    for (int d = t; d < Dd; d += 128) {
        float m = 0.f, v2 = 0.f;
        #pragma unroll
        for (int c = 0; c < NCH; c++) {
            size_t idx = (((size_t)c * Bb + b) * Kk + k) * Dd + d;
            m  += g_mupart[idx];
            v2 += g_v2part[idx];
        }
        m  /= denom;
        v2 /= denom;
        float sg = v2 - m * m * (2.f - s);
        g_mu[(size_t)bk_ * Dd + d] = m;
        g_sigma[(size_t)bk_ * Dd + d] = sg;
        float w = 1.f / (sg * sg + c_EPS);
        float q = g_q[(size_t)bk_ * Dd + d];
        g_w [(size_t)bk_ * Dd + d] = w;
        g_qw[(size_t)bk_ * Dd + d] = q * w;
        slog += logf(fabsf(sg) + c_EPS);
        sqwq += q * q * w;
    }
    #pragma unroll
    for (int o = 16; o; o >>= 1) {
        slog += __shfl_xor_sync(0xffffffffu, slog, o);
        sqwq += __shfl_xor_sync(0xffffffffu, sqwq, o);
    }
    __shared__ float sh[2][4];
    if ((t & 31) == 0) { sh[0][t >> 5] = slog; sh[1][t >> 5] = sqwq; }
    __syncthreads();
    if (t == 0) {
        float SL = sh[0][0] + sh[0][1] + sh[0][2] + sh[0][3];
        float SQ = sh[1][0] + sh[1][1] + sh[1][2] + sh[1][3];
        g_c1[bk_] = -0.5f * (float)Dd * c_LOG2PI - 0.5f * SL - 0.5f * SQ;
        g_mixing[bk_] = s / (float)Nn;
        g_S[bk_] = S;
    }
}

// ---------------- K6: fused outputs (slots | transposed attn) ----------------
__global__ void outputs(const float* __restrict__ noise_final, float* __restrict__ out) {
    int idx = blockIdx.x * 256 + threadIdx.x;
    if (idx < Bb * Kk * Dd) {
        float sg = fabsf(g_sigma[idx]);
        sg = fmaxf(sg, c_EPS);
        out[idx] = g_mu[idx] + sg * noise_final[idx];
    } else {
        int i2 = idx - Bb * Kk * Dd;       // 0..B*K*N-1
        int n = i2 & (Nn - 1);
        int k = (i2 >> 10) & (Kk - 1);
        int b = i2 >> 13;
        float denom = g_S[b * Kk + k] + c_EPS;
        out[idx] = g_attn[((size_t)b * Nn + n) * Kk + k] / denom;
    }
}

// ---------------- launcher ---------------------------------------------------
extern "C" void kernel_launch(void* const* d_in, const int* in_sizes, int n_in,
                              void* d_out, int out_size) {
    const float* embeddings = (const float*)d_in[0];
    const float* noise_init = (const float*)d_in[1];
    const float* noise_final= (const float*)d_in[2];
    const float* slots_mu   = (const float*)d_in[3];
    const float* slots_ls   = (const float*)d_in[4];
    const float* mixing     = (const float*)d_in[5];
    const float* Wk = (const float*)d_in[6];
    const float* bk = (const float*)d_in[7];
    const float* Wq = (const float*)d_in[8];
    const float* bq = (const float*)d_in[9];
    const float* Wv = (const float*)d_in[10];
    const float* bv = (const float*)d_in[11];
    const float* lng = (const float*)d_in[12];
    const float* lnb = (const float*)d_in[13];
    float* out = (float*)d_out;

    cudaFuncSetAttribute(mma_kv, cudaFuncAttributeMaxDynamicSharedMemorySize, MMA_SMEM);

    ln_split<<<Mtot, 128>>>(embeddings, lng, lnb);
    wt_split<<<dim3(32, 16), dim3(32, 8)>>>(Wk, Wv);
    init_slots_queries<<<Bb * Kk, 128>>>(noise_init, slots_mu, slots_ls, mixing, Wq, bq);
    mma_kv<<<dim3(Ntot / 128, Mtot / 128), 256, MMA_SMEM>>>(bk, bv);

    for (int it = 0; it < NITER; it++) {
        em_iter<<<dim3(Bb, NCH), 256>>>();
        reduce_update<<<Bb * Kk, 128>>>();
    }

    outputs<<<(Bb * Kk * Dd + Bb * Kk * Nn) / 256, 256>>>(noise_final, out);
}

// round 10
// speedup vs baseline: 1.1579x; 1.1579x over previous
#include <cuda_runtime.h>
#include <cuda_bf16.h>
#include <cstdint>
#include <stdint.h>
#include <math.h>

#define Bb 16
#define Nn 1024
#define Dd 512
#define Kk 8
#define NITER 3
#define NROWCHUNK 32     // gll_attn chunks (32 rows each)
#define NCHUNK 8         // mu_partial n-chunks (128 rows each)

#define Mtot (Bb*Nn)     // 16384
#define Ntot (2*Dd)      // 1024
#define LDA 40           // smem row stride (bf16): 32 + 8 pad, conflict-free ldmatrix
#define TILE_B (128*LDA*2)    // 10240 bytes
#define MMA_SMEM (2*4*TILE_B) // 81920

__device__ __constant__ float c_EPS = 1e-8f;
__device__ __constant__ float c_LNEPS = 1e-5f;
__device__ __constant__ float c_LOG2PI = 1.8378770664093453f;

// ---------------- scratch ----------------------------------------------------
__device__ float g_keys[Mtot*Dd];
__device__ float g_values[Mtot*Dd];
__device__ float g_q[Bb*Kk*Dd];
__device__ float g_sigma[Bb*Kk*Dd];
__device__ float g_w[Bb*Kk*Dd];
__device__ float g_qw[Bb*Kk*Dd];
__device__ float g_c1[Bb*Kk];
__device__ float g_mixing[Bb*Kk];
__device__ float g_attn[Bb*Nn*Kk];
__device__ float g_Spart[Bb*NROWCHUNK*Kk];
__device__ float g_S[Bb*Kk];
__device__ float g_mupart[NCHUNK*Bb*Kk*Dd];
__device__ float g_v2part[NCHUNK*Bb*Kk*Dd];
__device__ float g_mu[Bb*Kk*Dd];

__device__ __align__(16) __nv_bfloat16 g_Ahi[Mtot*Dd];
__device__ __align__(16) __nv_bfloat16 g_Alo[Mtot*Dd];
__device__ __align__(16) __nv_bfloat16 g_Bhi[Ntot*Dd];
__device__ __align__(16) __nv_bfloat16 g_Blo[Ntot*Dd];

// ---------------- PTX helpers ------------------------------------------------
__device__ __forceinline__ uint32_t smem_u32(const void* p) {
    uint32_t a;
    asm("{ .reg .u64 t; cvta.to.shared.u64 t, %1; cvt.u32.u64 %0, t; }" : "=r"(a) : "l"(p));
    return a;
}
__device__ __forceinline__ void cpasync16(uint32_t saddr, const void* g) {
    asm volatile("cp.async.ca.shared.global [%0], [%1], 16;" :: "r"(saddr), "l"(g));
}
__device__ __forceinline__ void ldm4(uint32_t* r, uint32_t addr) {
    asm volatile("ldmatrix.sync.aligned.m8n8.x4.shared.b16 {%0,%1,%2,%3}, [%4];"
        : "=r"(r[0]), "=r"(r[1]), "=r"(r[2]), "=r"(r[3]) : "r"(addr));
}
__device__ __forceinline__ void mma16816(float* c, const uint32_t* a, const uint32_t* b) {
    asm volatile(
        "mma.sync.aligned.m16n8k16.row.col.f32.bf16.bf16.f32 "
        "{%0,%1,%2,%3}, {%4,%5,%6,%7}, {%8,%9}, {%0,%1,%2,%3};"
        : "+f"(c[0]), "+f"(c[1]), "+f"(c[2]), "+f"(c[3])
        : "r"(a[0]), "r"(a[1]), "r"(a[2]), "r"(a[3]), "r"(b[0]), "r"(b[1]));
}

// ---------------- K0: LN stats + bf16 hi/lo split ----------------------------
__global__ __launch_bounds__(128) void ln_split(
    const float* __restrict__ E, const float* __restrict__ lng, const float* __restrict__ lnb)
{
    int row = blockIdx.x;
    int t = threadIdx.x;
    float4 v = ((const float4*)(E + (size_t)row * Dd))[t];
    float s = v.x + v.y + v.z + v.w;
    float s2 = v.x*v.x + v.y*v.y + v.z*v.z + v.w*v.w;
    #pragma unroll
    for (int o = 16; o; o >>= 1) {
        s  += __shfl_xor_sync(0xffffffffu, s,  o);
        s2 += __shfl_xor_sync(0xffffffffu, s2, o);
    }
    __shared__ float sh[2][4];
    if ((t & 31) == 0) { sh[0][t >> 5] = s; sh[1][t >> 5] = s2; }
    __syncthreads();
    float S  = sh[0][0] + sh[0][1] + sh[0][2] + sh[0][3];
    float S2 = sh[1][0] + sh[1][1] + sh[1][2] + sh[1][3];
    float m = S / (float)Dd;
    float var = S2 / (float)Dd - m * m;
    float rs = rsqrtf(var + c_LNEPS);

    float4 g4 = ((const float4*)lng)[t];
    float4 b4 = ((const float4*)lnb)[t];
    float y[4];
    y[0] = (v.x - m) * rs * g4.x + b4.x;
    y[1] = (v.y - m) * rs * g4.y + b4.y;
    y[2] = (v.z - m) * rs * g4.z + b4.z;
    y[3] = (v.w - m) * rs * g4.w + b4.w;
    __nv_bfloat16 hi[4], lo[4];
    #pragma unroll
    for (int i = 0; i < 4; i++) {
        hi[i] = __float2bfloat16(y[i]);
        lo[i] = __float2bfloat16(y[i] - __bfloat162float(hi[i]));
    }
    *(uint2*)(g_Ahi + (size_t)row * Dd + t * 4) = *(uint2*)hi;
    *(uint2*)(g_Alo + (size_t)row * Dd + t * 4) = *(uint2*)lo;
}

// ---------------- K1: W^T bf16 hi/lo split -----------------------------------
__global__ void wt_split(const float* __restrict__ Wk, const float* __restrict__ Wv) {
    __shared__ float tile[32][33];
    int n0 = blockIdx.x * 32;
    int k0 = blockIdx.y * 32;
    const float* W = (n0 < Dd) ? Wk : Wv;
    int nc0 = n0 & (Dd - 1);
    int tx = threadIdx.x, ty = threadIdx.y;
    #pragma unroll
    for (int i = ty; i < 32; i += 8)
        tile[i][tx] = W[(size_t)(k0 + i) * Dd + nc0 + tx];
    __syncthreads();
    #pragma unroll
    for (int i = ty; i < 32; i += 8) {
        float x = tile[tx][i];
        __nv_bfloat16 hi = __float2bfloat16(x);
        __nv_bfloat16 lo = __float2bfloat16(x - __bfloat162float(hi));
        g_Bhi[(size_t)(n0 + i) * Dd + k0 + tx] = hi;
        g_Blo[(size_t)(n0 + i) * Dd + k0 + tx] = lo;
    }
}

// ---------------- K2: HMMA bf16x3 GEMM (round-9 version, 169us) --------------
__global__ __launch_bounds__(256, 2) void mma_kv(
    const float* __restrict__ bk, const float* __restrict__ bv)
{
    extern __shared__ char dsm[];
    int tid = threadIdx.x, lane = tid & 31, wid = tid >> 5;
    int warp_m = wid >> 1, warp_n = wid & 1;
    int n0 = blockIdx.x * 128;
    int m0 = blockIdx.y * 128;

    float acc[2][8][4];
    #pragma unroll
    for (int i = 0; i < 2; i++)
        #pragma unroll
        for (int j = 0; j < 8; j++)
            #pragma unroll
            for (int q = 0; q < 4; q++) acc[i][j][q] = 0.f;

    const int lrow = tid >> 1;
    const int lseg = (tid & 1) * 2;

    #pragma unroll
    for (int j = 0; j < 2; j++) {
        int off = (lseg + j) * 8;
        size_t ao = (size_t)(m0 + lrow) * Dd + off;
        size_t bo = (size_t)(n0 + lrow) * Dd + off;
        uint32_t so = lrow * LDA * 2 + off * 2;
        cpasync16(smem_u32(dsm + 0*TILE_B + so), g_Ahi + ao);
        cpasync16(smem_u32(dsm + 1*TILE_B + so), g_Alo + ao);
        cpasync16(smem_u32(dsm + 2*TILE_B + so), g_Bhi + bo);
        cpasync16(smem_u32(dsm + 3*TILE_B + so), g_Blo + bo);
    }
    asm volatile("cp.async.commit_group;" ::: "memory");

    for (int kc = 0; kc < 16; kc++) {
        int buf = kc & 1;
        char* cur = dsm + buf * 4 * TILE_B;
        if (kc < 15) {
            char* nxt = dsm + (buf ^ 1) * 4 * TILE_B;
            int kn = (kc + 1) * 32;
            #pragma unroll
            for (int j = 0; j < 2; j++) {
                int off = (lseg + j) * 8;
                size_t ao = (size_t)(m0 + lrow) * Dd + kn + off;
                size_t bo = (size_t)(n0 + lrow) * Dd + kn + off;
                uint32_t so = lrow * LDA * 2 + off * 2;
                cpasync16(smem_u32(nxt + 0*TILE_B + so), g_Ahi + ao);
                cpasync16(smem_u32(nxt + 1*TILE_B + so), g_Alo + ao);
                cpasync16(smem_u32(nxt + 2*TILE_B + so), g_Bhi + bo);
                cpasync16(smem_u32(nxt + 3*TILE_B + so), g_Blo + bo);
            }
            asm volatile("cp.async.commit_group;" ::: "memory");
            asm volatile("cp.async.wait_group 1;" ::: "memory");
        } else {
            asm volatile("cp.async.wait_group 0;" ::: "memory");
        }
        __syncthreads();

        const __nv_bfloat16* sAhi = (const __nv_bfloat16*)(cur + 0*TILE_B);
        const __nv_bfloat16* sAlo = (const __nv_bfloat16*)(cur + 1*TILE_B);
        const __nv_bfloat16* sBhi = (const __nv_bfloat16*)(cur + 2*TILE_B);
        const __nv_bfloat16* sBlo = (const __nv_bfloat16*)(cur + 3*TILE_B);

        #pragma unroll
        for (int ks = 0; ks < 2; ks++) {
            uint32_t ahi[2][4], alo[2][4];
            #pragma unroll
            for (int mi = 0; mi < 2; mi++) {
                int row = warp_m * 32 + mi * 16 + (lane & 15);
                int col = ks * 16 + (lane >> 4) * 8;
                ldm4(ahi[mi], smem_u32(&sAhi[row * LDA + col]));
                ldm4(alo[mi], smem_u32(&sAlo[row * LDA + col]));
            }
            #pragma unroll
            for (int h = 0; h < 2; h++) {
                uint32_t bhi[4][2], blo[4][2];
                #pragma unroll
                for (int jj = 0; jj < 2; jj++) {
                    int nrow = warp_n * 64 + h * 32 + jj * 16 + (lane & 7) + ((lane >> 4) << 3);
                    int col = ks * 16 + ((lane >> 3) & 1) * 8;
                    uint32_t r4[4];
                    ldm4(r4, smem_u32(&sBhi[nrow * LDA + col]));
                    bhi[2*jj][0] = r4[0]; bhi[2*jj][1] = r4[1];
                    bhi[2*jj+1][0] = r4[2]; bhi[2*jj+1][1] = r4[3];
                    ldm4(r4, smem_u32(&sBlo[nrow * LDA + col]));
                    blo[2*jj][0] = r4[0]; blo[2*jj][1] = r4[1];
                    blo[2*jj+1][0] = r4[2]; blo[2*jj+1][1] = r4[3];
                }
                #pragma unroll
                for (int mi = 0; mi < 2; mi++)
                    #pragma unroll
                    for (int j2 = 0; j2 < 4; j2++) {
                        int nj = h * 4 + j2;
                        mma16816(acc[mi][nj], ahi[mi], bhi[j2]);
                        mma16816(acc[mi][nj], ahi[mi], blo[j2]);
                        mma16816(acc[mi][nj], alo[mi], bhi[j2]);
                    }
            }
        }
        __syncthreads();
    }

    const bool isK = (n0 < Dd);
    float* Dst = isK ? g_keys : g_values;
    const float* bias = isK ? bk : bv;
    int nbase = (isK ? n0 : n0 - Dd) + warp_n * 64;
    int mbase = m0 + warp_m * 32;
    int r = lane >> 2, cp = 2 * (lane & 3);
    #pragma unroll
    for (int mi = 0; mi < 2; mi++) {
        #pragma unroll
        for (int nj = 0; nj < 8; nj++) {
            int n = nbase + nj * 8 + cp;
            float b0 = bias[n], b1 = bias[n + 1];
            int m = mbase + mi * 16 + r;
            float2 o0 = { acc[mi][nj][0] + b0, acc[mi][nj][1] + b1 };
            float2 o1 = { acc[mi][nj][2] + b0, acc[mi][nj][3] + b1 };
            *(float2*)&Dst[(size_t)m * Dd + n] = o0;
            *(float2*)&Dst[(size_t)(m + 8) * Dd + n] = o1;
        }
    }
}

// ---------------- K3: slots, queries, AND iter-0 prep (w/qw/c1) --------------
__global__ void init_slots_queries(
    const float* __restrict__ noise_init, const float* __restrict__ slots_mu,
    const float* __restrict__ slots_ls,   const float* __restrict__ mix_in,
    const float* __restrict__ Wq,         const float* __restrict__ bq)
{
    int bk_ = blockIdx.x;
    int b = bk_ >> 3, k = bk_ & 7;
    __shared__ float slot[Dd];
    int t = threadIdx.x;
    for (int d = t; d < Dd; d += 128) {
        float sg = expf(slots_ls[k * Dd + d]);
        slot[d] = slots_mu[k * Dd + d] + sg * noise_init[((size_t)b * Kk + k) * Dd + d];
        g_sigma[((size_t)b * Kk + k) * Dd + d] = sg;
    }
    if (t == 0) g_mixing[b * Kk + k] = mix_in[k];
    __syncthreads();
    float slog = 0.f, sqwq = 0.f;
    for (int j = t; j < Dd; j += 128) {
        float acc = bq[j];
        for (int d = 0; d < Dd; d++) acc += slot[d] * Wq[(size_t)d * Dd + j];
        g_q[((size_t)bk_) * Dd + j] = acc;
        float sg = g_sigma[(size_t)bk_ * Dd + j];
        float w = 1.f / (sg * sg + c_EPS);
        g_w [(size_t)bk_ * Dd + j] = w;
        g_qw[(size_t)bk_ * Dd + j] = acc * w;
        slog += logf(fabsf(sg) + c_EPS);
        sqwq += acc * acc * w;
    }
    #pragma unroll
    for (int o = 16; o; o >>= 1) {
        slog += __shfl_xor_sync(0xffffffffu, slog, o);
        sqwq += __shfl_xor_sync(0xffffffffu, sqwq, o);
    }
    __shared__ float sh[2][4];
    if ((t & 31) == 0) { sh[0][t >> 5] = slog; sh[1][t >> 5] = sqwq; }
    __syncthreads();
    if (t == 0) {
        float SL = sh[0][0] + sh[0][1] + sh[0][2] + sh[0][3];
        float SQ = sh[1][0] + sh[1][1] + sh[1][2] + sh[1][3];
        g_c1[bk_] = -0.5f * (float)Dd * c_LOG2PI - 0.5f * SL - 0.5f * SQ;
    }
}

// ---------------- K4: gll + K-normalized attn + colsum partials (round-8) ----
__global__ __launch_bounds__(256) void gll_attn() {
    int b = blockIdx.x, chunk = blockIdx.y;
    int t = threadIdx.x, warp = t >> 5, lane = t & 31;
    __shared__ float sw[Kk * Dd];
    __shared__ float sqw[Kk * Dd];
    __shared__ float c1s[Kk], mixs[Kk];
    __shared__ float wcs[8][Kk];
    for (int i = t; i < Kk * Dd; i += 256) {
        sw [i] = g_w [(size_t)b * Kk * Dd + i];
        sqw[i] = g_qw[(size_t)b * Kk * Dd + i];
    }
    if (t < Kk) { c1s[t] = g_c1[b * Kk + t]; mixs[t] = g_mixing[b * Kk + t]; }
    __syncthreads();

    float cs = 0.f;
    int rbase = chunk * 32 + warp * 4;
    for (int rr = 0; rr < 4; rr++) {
        int r = rbase + rr;
        const float* krow = g_keys + ((size_t)b * Nn + r) * Dd;
        float kk[Kk], kq[Kk];
        #pragma unroll
        for (int k = 0; k < Kk; k++) { kk[k] = 0.f; kq[k] = 0.f; }
        #pragma unroll
        for (int i = 0; i < 16; i++) {
            int d = lane + 32 * i;
            float kv = krow[d];
            float kv2 = kv * kv;
            #pragma unroll
            for (int k = 0; k < Kk; k++) {
                kk[k] += kv2 * sw [k * Dd + d];
                kq[k] += kv  * sqw[k * Dd + d];
            }
        }
        #pragma unroll
        for (int o = 16; o; o >>= 1)
            #pragma unroll
            for (int k = 0; k < Kk; k++) {
                kk[k] += __shfl_xor_sync(0xffffffffu, kk[k], o);
                kq[k] += __shfl_xor_sync(0xffffffffu, kq[k], o);
            }
        float au[Kk], rsum = 0.f;
        #pragma unroll
        for (int k = 0; k < Kk; k++) {
            float gll = c1s[k] - 0.5f * kk[k] + kq[k];
            au[k] = mixs[k] * gll;
            rsum += au[k];
        }
        float inv = 1.f / rsum;
        if (lane < Kk) {
            float a = au[lane] * inv;
            g_attn[((size_t)b * Nn + r) * Kk + lane] = a;
            cs += a;
        }
    }
    if (lane < Kk) wcs[warp][lane] = cs;
    __syncthreads();
    if (t < Kk) {
        float S = 0.f;
        #pragma unroll
        for (int w = 0; w < 8; w++) S += wcs[w][t];   // fixed order
        g_Spart[((size_t)b * NROWCHUNK + chunk) * Kk + t] = S;
    }
}

// ---------------- K5: mu / E[v^2] partials (round-8) -------------------------
__global__ __launch_bounds__(128) void mu_partial() {
    int b = blockIdx.x, dt = blockIdx.y, nc = blockIdx.z, t = threadIdx.x;
    int d = dt * 128 + t;
    int n0 = nc * 128;
    __shared__ float att[128][Kk];
    {
        const float4* src = (const float4*)(g_attn + ((size_t)b * Nn + n0 + t) * Kk);
        float4 a0 = src[0], a1 = src[1];
        att[t][0] = a0.x; att[t][1] = a0.y; att[t][2] = a0.z; att[t][3] = a0.w;
        att[t][4] = a1.x; att[t][5] = a1.y; att[t][6] = a1.z; att[t][7] = a1.w;
    }
    __syncthreads();
    float mu_[Kk], v2_[Kk];
    #pragma unroll
    for (int k = 0; k < Kk; k++) { mu_[k] = 0.f; v2_[k] = 0.f; }
    for (int i = 0; i < 128; i++) {
        float v = g_values[((size_t)b * Nn + n0 + i) * Dd + d];
        float vv = v * v;
        #pragma unroll
        for (int k = 0; k < Kk; k++) {
            float a = att[i][k];
            mu_[k] += a * v;
            v2_[k] += a * vv;
        }
    }
    #pragma unroll
    for (int k = 0; k < Kk; k++) {
        size_t idx = (((size_t)nc * Bb + b) * Kk + k) * Dd + d;
        g_mupart[idx] = mu_[k];
        g_v2part[idx] = v2_[k];
    }
}

// ---------------- K6: reduce partials; update + next-iter prep ---------------
__global__ void reduce_update() {
    int bk_ = blockIdx.x;
    int b = bk_ >> 3, k = bk_ & 7;
    int t = threadIdx.x;
    float S = 0.f;
    #pragma unroll
    for (int c = 0; c < NROWCHUNK; c++)
        S += g_Spart[((size_t)b * NROWCHUNK + c) * Kk + k];   // fixed order
    float denom = S + c_EPS;
    float s = S / denom;
    float slog = 0.f, sqwq = 0.f;
    for (int d = t; d < Dd; d += 128) {
        float m = 0.f, v2 = 0.f;
        #pragma unroll
        for (int c = 0; c < NCHUNK; c++) {
            size_t idx = (((size_t)c * Bb + b) * Kk + k) * Dd + d;
            m  += g_mupart[idx];
            v2 += g_v2part[idx];
        }
        m  /= denom;
        v2 /= denom;
        float sg = v2 - m * m * (2.f - s);
        g_mu[(size_t)bk_ * Dd + d] = m;
        g_sigma[(size_t)bk_ * Dd + d] = sg;
        float w = 1.f / (sg * sg + c_EPS);
        float q = g_q[(size_t)bk_ * Dd + d];
        g_w [(size_t)bk_ * Dd + d] = w;
        g_qw[(size_t)bk_ * Dd + d] = q * w;
        slog += logf(fabsf(sg) + c_EPS);
        sqwq += q * q * w;
    }
    #pragma unroll
    for (int o = 16; o; o >>= 1) {
        slog += __shfl_xor_sync(0xffffffffu, slog, o);
        sqwq += __shfl_xor_sync(0xffffffffu, sqwq, o);
    }
    __shared__ float sh[2][4];
    if ((t & 31) == 0) { sh[0][t >> 5] = slog; sh[1][t >> 5] = sqwq; }
    __syncthreads();
    if (t == 0) {
        float SL = sh[0][0] + sh[0][1] + sh[0][2] + sh[0][3];
        float SQ = sh[1][0] + sh[1][1] + sh[1][2] + sh[1][3];
        g_c1[bk_] = -0.5f * (float)Dd * c_LOG2PI - 0.5f * SL - 0.5f * SQ;
        g_mixing[bk_] = s / (float)Nn;
        g_S[bk_] = S;
    }
}

// ---------------- K7: fused outputs ------------------------------------------
__global__ void outputs(const float* __restrict__ noise_final, float* __restrict__ out) {
    int idx = blockIdx.x * 256 + threadIdx.x;
    if (idx < Bb * Kk * Dd) {
        float sg = fabsf(g_sigma[idx]);
        sg = fmaxf(sg, c_EPS);
        out[idx] = g_mu[idx] + sg * noise_final[idx];
    } else {
        int i2 = idx - Bb * Kk * Dd;
        int n = i2 & (Nn - 1);
        int k = (i2 >> 10) & (Kk - 1);
        int b = i2 >> 13;
        float denom = g_S[b * Kk + k] + c_EPS;
        out[idx] = g_attn[((size_t)b * Nn + n) * Kk + k] / denom;
    }
}

// ---------------- launcher ---------------------------------------------------
extern "C" void kernel_launch(void* const* d_in, const int* in_sizes, int n_in,
                              void* d_out, int out_size) {
    const float* embeddings = (const float*)d_in[0];
    const float* noise_init = (const float*)d_in[1];
    const float* noise_final= (const float*)d_in[2];
    const float* slots_mu   = (const float*)d_in[3];
    const float* slots_ls   = (const float*)d_in[4];
    const float* mixing     = (const float*)d_in[5];
    const float* Wk = (const float*)d_in[6];
    const float* bk = (const float*)d_in[7];
    const float* Wq = (const float*)d_in[8];
    const float* bq = (const float*)d_in[9];
    const float* Wv = (const float*)d_in[10];
    const float* bv = (const float*)d_in[11];
    const float* lng = (const float*)d_in[12];
    const float* lnb = (const float*)d_in[13];
    float* out = (float*)d_out;

    cudaFuncSetAttribute(mma_kv, cudaFuncAttributeMaxDynamicSharedMemorySize, MMA_SMEM);

    ln_split<<<Mtot, 128>>>(embeddings, lng, lnb);
    wt_split<<<dim3(32, 16), dim3(32, 8)>>>(Wk, Wv);
    init_slots_queries<<<Bb * Kk, 128>>>(noise_init, slots_mu, slots_ls, mixing, Wq, bq);
    mma_kv<<<dim3(Ntot / 128, Mtot / 128), 256, MMA_SMEM>>>(bk, bv);

    for (int it = 0; it < NITER; it++) {
        gll_attn<<<dim3(Bb, NROWCHUNK), 256>>>();
        mu_partial<<<dim3(Bb, 4, NCHUNK), 128>>>();
        reduce_update<<<Bb * Kk, 128>>>();
    }

    outputs<<<(Bb * Kk * Dd + Bb * Kk * Nn) / 256, 256>>>(noise_final, out);
}